// round 3
// baseline (speedup 1.0000x reference)
#include <cuda_runtime.h>
#include <cstdint>

// Problem constants (fixed by setup_inputs)
#define BATCH       4
#define KGT         64
#define HW_DIM      80
#define NUNIQ       25600          // A(4) * 80 * 80 unique anchors
#define NANCH       102400         // 4 reps * NUNIQ
#define OV_ELEMS    (BATCH * NANCH * KGT)   // 26,214,400
#define MAX_ELEMS   (BATCH * NANCH)         // 409,600

#define ROWS_PER_BLOCK   128
#define PAIRS_PER_WARP   8        // 8 warps * 8 pairs * 2 rows = 128 rows/block
#define BLOCKS_PER_BATCH (NUNIQ / ROWS_PER_BLOCK)   // 200
#define GRID_BLOCKS      (BATCH * BLOCKS_PER_BATCH) // 800

__device__ unsigned int g_gtmax[BATCH * KGT];

// Order-preserving float <-> uint encoding for atomicMax on floats
__device__ __forceinline__ unsigned enc_f(float f) {
    unsigned u = __float_as_uint(f);
    return (u & 0x80000000u) ? ~u : (u | 0x80000000u);
}
__device__ __forceinline__ float dec_f(unsigned u) {
    return __uint_as_float((u & 0x80000000u) ? (u & 0x7fffffffu) : ~u);
}

__global__ void init_gtmax_kernel() {
    if (threadIdx.x < BATCH * KGT) g_gtmax[threadIdx.x] = 0u;  // encoded minimum
}

__global__ void decode_gtmax_kernel(float* __restrict__ out_gt) {
    if (threadIdx.x < BATCH * KGT) out_gt[threadIdx.x] = dec_f(g_gtmax[threadIdx.x]);
}

__global__ __launch_bounds__(256)
void anchor_overlap_kernel(const float* __restrict__ gt_boxes,  // (B, K, 5)
                           float* __restrict__ out)
{
    const int b      = blockIdx.x / BLOCKS_PER_BATCH;
    const int blk    = blockIdx.x % BLOCKS_PER_BATCH;
    const int n_base = blk * ROWS_PER_BLOCK;

    const int tid   = threadIdx.x;
    const int lane  = tid & 31;
    const int warp  = tid >> 5;
    const int q     = lane & 15;     // which k-quad
    const int sub   = lane >> 4;     // which row of the pair
    const int kbase = q * 4;

    float* __restrict__ out_ov  = out;
    float* __restrict__ out_max = out + OV_ELEMS;
    float* __restrict__ out_arg = out + OV_ELEMS + MAX_ELEMS;

    __shared__ float    smax[ROWS_PER_BLOCK];
    __shared__ float    sarg[ROWS_PER_BLOCK];
    __shared__ unsigned sg[KGT];

    if (tid < KGT) sg[tid] = 0u;

    // ---- preload this lane's 4 gt boxes into registers ----
    float g0[4], g1[4], g2[4], g3[4], garea[4];
    bool  gz[4];
#pragma unroll
    for (int j = 0; j < 4; j++) {
        const float* g = gt_boxes + ((size_t)b * KGT + (kbase + j)) * 5;
        float a0 = g[0], a1 = g[1], a2 = g[2], a3 = g[3];
        g0[j] = a0; g1[j] = a1; g2[j] = a2; g3[j] = a3;
        float gx = __fadd_rn(__fsub_rn(a2, a0), 1.0f);
        float gy = __fadd_rn(__fsub_rn(a3, a1), 1.0f);
        garea[j] = __fmul_rn(gx, gy);
        gz[j]    = (gx == 1.0f) && (gy == 1.0f);
    }

    const float NEG_INF = __int_as_float(0xff800000);
    float gmax[4] = {NEG_INF, NEG_INF, NEG_INF, NEG_INF};

    __syncthreads();   // sg init visible before shared atomics later

#pragma unroll 1
    for (int p = 0; p < PAIRS_PER_WARP; p++) {
        const int lrow = (warp * PAIRS_PER_WARP + p) * 2 + sub;
        const int n    = n_base + lrow;               // unique anchor index [0, 25600)

        // ---- anchor geometry (exactly as reference) ----
        int a  = n / (HW_DIM * HW_DIM);
        int r  = n - a * (HW_DIM * HW_DIM);
        int yy = r / HW_DIM;
        int xx = r - yy * HW_DIM;

        float s  = (float)(2 << a);                   // 2,4,8,16
        float h2 = 0.5f * s;
        float fx = (float)xx, fy = (float)yy;
        float x0 = fx - h2, y0 = fy - h2;
        float x2 = x0 + s,  y2 = y0 + s;
        const float bound = (float)(HW_DIM - 1);
        float x0c = fminf(fmaxf(x0, 0.0f), bound);
        float y0c = fminf(fmaxf(y0, 0.0f), bound);
        float x2c = fminf(fmaxf(x2, 0.0f), bound);
        float y2c = fminf(fmaxf(y2, 0.0f), bound);

        // anchors stored as [x0c, y0c, x2c-x0c, y2c-y0c] in the reference
        float A0 = x0c, A1 = y0c;
        float A2 = __fsub_rn(x2c, x0c);
        float A3 = __fsub_rn(y2c, y0c);

        float anx    = __fadd_rn(__fsub_rn(A2, A0), 1.0f);
        float any_   = __fadd_rn(__fsub_rn(A3, A1), 1.0f);
        float anarea = __fmul_rn(anx, any_);
        bool  anz    = (anx == 1.0f) && (any_ == 1.0f);

        float ovj[4];
        float mval = NEG_INF;
        int   midx = 0;
#pragma unroll
        for (int j = 0; j < 4; j++) {
            float iw = __fadd_rn(__fsub_rn(fminf(A2, g2[j]), fmaxf(A0, g0[j])), 1.0f);
            iw = fmaxf(iw, 0.0f);
            float ih = __fadd_rn(__fsub_rn(fminf(A3, g3[j]), fmaxf(A1, g1[j])), 1.0f);
            ih = fmaxf(ih, 0.0f);
            float inter = __fmul_rn(iw, ih);
            float ua    = __fsub_rn(__fadd_rn(anarea, garea[j]), inter);
            float ov    = __fdiv_rn(inter, ua);       // IEEE div, matches XLA
            if (gz[j]) ov = 0.0f;
            if (anz)   ov = -1.0f;
            ovj[j]  = ov;
            gmax[j] = fmaxf(gmax[j], ov);
            if (ov > mval) { mval = ov; midx = kbase + j; }  // first-index ties
        }

        // ---- 16-lane butterfly argmax reduction (first-index on ties) ----
#pragma unroll
        for (int d = 1; d < 16; d <<= 1) {
            float o  = __shfl_xor_sync(0xffffffffu, mval, d);
            int   oi = __shfl_xor_sync(0xffffffffu, midx, d);
            if (o > mval || (o == mval && oi < midx)) { mval = o; midx = oi; }
        }
        if (q == 0) { smax[lrow] = mval; sarg[lrow] = (float)midx; }

        // ---- write overlaps row to all 4 replicated anchor blocks ----
        // Streaming stores: this 100 MB block is written once, never re-read here.
        float4 vv = make_float4(ovj[0], ovj[1], ovj[2], ovj[3]);
        size_t rowbase = ((size_t)b * NANCH + n) * KGT + kbase;
#pragma unroll
        for (int rep = 0; rep < 4; rep++) {
            __stcs((float4*)(out_ov + rowbase + (size_t)rep * (NUNIQ * KGT)), vv);
        }
    }

    // ---- gt_max: block combine in shared, then one global atomic per k ----
#pragma unroll
    for (int j = 0; j < 4; j++) {
        atomicMax(&sg[kbase + j], enc_f(gmax[j]));
    }
    __syncthreads();

    if (tid < KGT) {
        atomicMax(&g_gtmax[b * KGT + tid], sg[tid]);
    }

    // ---- coalesced max/argmax writeout (rows contiguous per rep) ----
    if (tid < ROWS_PER_BLOCK) {
        float mv = smax[tid];
        float av = sarg[tid];
        size_t base = (size_t)b * NANCH + n_base + tid;
#pragma unroll
        for (int rep = 0; rep < 4; rep++) {
            out_max[base + (size_t)rep * NUNIQ] = mv;
            out_arg[base + (size_t)rep * NUNIQ] = av;
        }
    }
}

extern "C" void kernel_launch(void* const* d_in, const int* in_sizes, int n_in,
                              void* d_out, int out_size)
{
    (void)out_size;
    // Select gt_boxes by its exact element count (B*K*5 = 1280); cls_scores is 204800.
    const float* gt_boxes = (const float*)d_in[n_in > 1 ? 1 : 0];
    for (int i = 0; i < n_in; i++) {
        if (in_sizes[i] == BATCH * KGT * 5) { gt_boxes = (const float*)d_in[i]; break; }
    }
    float* out = (float*)d_out;

    float* out_gt = out + OV_ELEMS + 2 * (size_t)MAX_ELEMS;

    init_gtmax_kernel<<<1, 256>>>();
    anchor_overlap_kernel<<<GRID_BLOCKS, 256>>>(gt_boxes, out);
    decode_gtmax_kernel<<<1, 256>>>(out_gt);
}